// round 3
// baseline (speedup 1.0000x reference)
#include <cuda_runtime.h>
#include <math.h>

// ---------------------------------------------------------------------------
// Problem constants: B=8, T=10, H=W=64, Cin=1, F=64, 4F=256, k=3x3 SAME.
// Output: [2 layers][2 (h,c)][8][64][64][64] fp32 = 8,388,608 floats.
// ---------------------------------------------------------------------------

#define HW        64
#define FDIM      64
#define C4        256
#define NPIX      4096           // 64*64
#define SEG       2097152        // 8*4096*64  (one h or c tensor)

// Scratch (device globals: the sanctioned allocation-free workaround)
__device__ float g_xg0[10 * 8 * NPIX * C4];   // 83,886,080 floats
__device__ float g_xg1[10 * 8 * NPIX * C4];
__device__ float g_out0[10 * 8 * NPIX * FDIM];
__device__ float g_h[2][SEG];
__device__ float g_c[SEG];

__device__ __forceinline__ float hsig(float x) {
    return fminf(fmaxf(0.2f * x + 0.5f, 0.0f), 1.0f);
}

// ---------------------------------------------------------------------------
// Zero-init h (ping buffer) and c
// ---------------------------------------------------------------------------
__global__ void zero_hc() {
    int i = blockIdx.x * blockDim.x + threadIdx.x;
    if (i < SEG) { g_h[0][i] = 0.0f; g_c[i] = 0.0f; }
}

// Copy final h (in g_h[0] after 10 steps) and c into the output stack
__global__ void gather_out(float* __restrict__ out, int layer) {
    int i = blockIdx.x * blockDim.x + threadIdx.x;
    if (i < SEG) {
        out[(size_t)layer * 2 * SEG + i]       = g_h[0][i];
        out[(size_t)layer * 2 * SEG + SEG + i] = g_c[i];
    }
}

// ---------------------------------------------------------------------------
// Layer-0 input conv (Cin=1): xg0[img][pos][256] = b0 + conv(x_img, Wx0)
// img = b*10 + t (matches x layout [B,T,H,W,1]). 16x16 tile per block,
// thread = output channel, weights in registers, patch broadcast from smem.
// ---------------------------------------------------------------------------
__global__ void conv_l0(const float* __restrict__ x, const float* __restrict__ w,
                        const float* __restrict__ b, float* __restrict__ xg) {
    __shared__ float ps[18 * 18];
    __shared__ float ws[9 * C4];

    int img = blockIdx.y;
    int by0 = (blockIdx.x >> 2) * 16;
    int bx0 = (blockIdx.x & 3) * 16;
    int tid = threadIdx.x;

    for (int i = tid; i < 324; i += 256) {
        int ly = i / 18, lx = i - ly * 18;
        int gy = by0 + ly - 1, gx = bx0 + lx - 1;
        float v = 0.0f;
        if (gy >= 0 && gy < HW && gx >= 0 && gx < HW)
            v = x[(size_t)img * NPIX + gy * HW + gx];
        ps[i] = v;
    }
    for (int i = tid; i < 9 * C4; i += 256) ws[i] = w[i];
    __syncthreads();

    float wr[9];
#pragma unroll
    for (int tp = 0; tp < 9; ++tp) wr[tp] = ws[tp * C4 + tid];
    float bv = b[tid];

    for (int p = 0; p < 256; ++p) {
        int py = p >> 4, px = p & 15;
        float a = bv;
#pragma unroll
        for (int tp = 0; tp < 9; ++tp) {
            int dy = tp / 3, dx = tp - 3 * dy;
            a += ps[(py + dy) * 18 + (px + dx)] * wr[tp];
        }
        xg[((size_t)img * NPIX + (by0 + py) * HW + (bx0 + px)) * C4 + tid] = a;
    }
}

// ---------------------------------------------------------------------------
// Core implicit-GEMM 3x3 conv, 64 in -> 256 out channels, 8x8 spatial tile.
// MODE STEP=1: acc init from xg (bias included), fused LSTM epilogue:
//     c' = hs(f)*c + hs(i)*tanh(g);  h' = hs(o)*tanh(c');  optional out_seq.
// MODE STEP=0: acc init from bias; stores raw gates to out_gates (xg buffer).
//
// smem: hsm[64ch][10][10] patch (ch-major -> h reads are warp broadcasts),
//       wsm 32x256 weight chunk stored j/cc-permuted for conflict-free LDS.128.
// Thread (pc=tid/16, cc=tid%16): 4 positions x 16 channels register tile.
// ---------------------------------------------------------------------------
template <int STEP>
__global__ __launch_bounds__(256, 2)
void conv_main(const float* __restrict__ in,        // [nimg][64][64][64]
               const float* __restrict__ W,         // [3][3][64][256]
               const float* __restrict__ xg_or_b,   // STEP: xg base; else bias[256]
               float* __restrict__ out_gates,       // !STEP: gates out
               float* __restrict__ cbuf,
               float* __restrict__ hout,
               float* __restrict__ outseq,
               int t) {
    extern __shared__ float smem[];
    float*  hsm  = smem;                       // 6400 floats
    float4* wsm4 = (float4*)(smem + 6400);     // 2048 float4 (8192 floats)

    int img = blockIdx.y;
    int by0 = (blockIdx.x >> 3) * 8;
    int bx0 = (blockIdx.x & 7) * 8;
    int tid = threadIdx.x;
    int pc = tid >> 4, cc = tid & 15;
    int py = pc >> 1, px0 = (pc & 1) * 4;

    // Load 10x10x64 input patch, channel-major in smem
    const float* inb = in + (size_t)img * NPIX * FDIM;
    for (int i = tid; i < 6400; i += 256) {
        int pix = i >> 6, ch = i & 63;
        int ly = pix / 10, lx = pix - ly * 10;
        int gy = by0 + ly - 1, gx = bx0 + lx - 1;
        float v = 0.0f;
        if (gy >= 0 && gy < HW && gx >= 0 && gx < HW)
            v = inb[((gy << 6) + gx) * FDIM + ch];
        hsm[ch * 100 + pix] = v;
    }

    // Init accumulators
    float4 acc[4][4];
    if (STEP) {
        const float* xgb = xg_or_b + (size_t)(img * 10 + t) * NPIX * C4;
#pragma unroll
        for (int i = 0; i < 4; ++i) {
            int pos = pc * 4 + i;
            int gy = by0 + (pos >> 3), gx = bx0 + (pos & 7);
            const float4* xp = (const float4*)(xgb + (size_t)((gy << 6) + gx) * C4);
#pragma unroll
            for (int j = 0; j < 4; ++j) acc[i][j] = xp[(cc << 2) + j];
        }
    } else {
        const float4* bp = (const float4*)xg_or_b;
        float4 bv[4];
#pragma unroll
        for (int j = 0; j < 4; ++j) bv[j] = bp[(cc << 2) + j];
#pragma unroll
        for (int i = 0; i < 4; ++i)
#pragma unroll
            for (int j = 0; j < 4; ++j) acc[i][j] = bv[j];
    }

    // Main loop: 9 taps x 2 chunks of 32 input channels
    for (int tap = 0; tap < 9; ++tap) {
        int dy = tap / 3, dx = tap - 3 * dy;
        for (int chunk = 0; chunk < 2; ++chunk) {
            __syncthreads();   // (1st iter: hsm ready; later: previous wsm reads done)
            const float4* wg = (const float4*)(W + (size_t)(tap * 64 + chunk * 32) * C4);
#pragma unroll
            for (int i = 0; i < 8; ++i) {
                int gi = tid + i * 256;                // 0..2047 float4s
                int kc = gi >> 6, c4 = gi & 63;        // c4 = cc*4 + j in source
                wsm4[(kc << 6) + ((c4 & 3) << 4) + (c4 >> 2)] = wg[gi];
            }
            __syncthreads();

            const float* hp = hsm + (chunk * 32) * 100 + (py + dy) * 10 + (px0 + dx);
#pragma unroll 4
            for (int kc = 0; kc < 32; ++kc) {
                const float4* wr2 = wsm4 + (kc << 6) + cc;
                float4 wv[4];
#pragma unroll
                for (int j = 0; j < 4; ++j) wv[j] = wr2[j * 16];
                float hv[4];
#pragma unroll
                for (int i = 0; i < 4; ++i) hv[i] = hp[kc * 100 + i];
#pragma unroll
                for (int i = 0; i < 4; ++i) {
#pragma unroll
                    for (int j = 0; j < 4; ++j) {
                        acc[i][j].x += hv[i] * wv[j].x;
                        acc[i][j].y += hv[i] * wv[j].y;
                        acc[i][j].z += hv[i] * wv[j].z;
                        acc[i][j].w += hv[i] * wv[j].w;
                    }
                }
            }
        }
    }

    if (STEP) {
        // Exchange gates through smem (i/f/g/o live in different threads)
        __syncthreads();
        float4* g4 = (float4*)smem;   // 64 pos x 64 float4 = 64 KB
#pragma unroll
        for (int i = 0; i < 4; ++i) {
            int pos = pc * 4 + i;
#pragma unroll
            for (int j = 0; j < 4; ++j) g4[(pos << 6) + (cc << 2) + j] = acc[i][j];
        }
        __syncthreads();
#pragma unroll
        for (int r = 0; r < 4; ++r) {
            int wk = r * 256 + tid;
            int pos = wk >> 4, fq = wk & 15;
            const float* gp = smem + (pos << 8);
            float4 ig = *(const float4*)(gp +       (fq << 2));
            float4 fg = *(const float4*)(gp +  64 + (fq << 2));
            float4 gg = *(const float4*)(gp + 128 + (fq << 2));
            float4 og = *(const float4*)(gp + 192 + (fq << 2));
            int gy = by0 + (pos >> 3), gx = bx0 + (pos & 7);
            size_t hidx = ((size_t)img * NPIX + (gy << 6) + gx) * FDIM + (fq << 2);
            float4 cold = *(const float4*)(cbuf + hidx);
            float4 cn, hn;
            cn.x = hsig(fg.x) * cold.x + hsig(ig.x) * tanhf(gg.x);
            cn.y = hsig(fg.y) * cold.y + hsig(ig.y) * tanhf(gg.y);
            cn.z = hsig(fg.z) * cold.z + hsig(ig.z) * tanhf(gg.z);
            cn.w = hsig(fg.w) * cold.w + hsig(ig.w) * tanhf(gg.w);
            hn.x = hsig(og.x) * tanhf(cn.x);
            hn.y = hsig(og.y) * tanhf(cn.y);
            hn.z = hsig(og.z) * tanhf(cn.z);
            hn.w = hsig(og.w) * tanhf(cn.w);
            *(float4*)(cbuf + hidx) = cn;
            *(float4*)(hout + hidx) = hn;
            if (outseq) {
                size_t oidx = ((size_t)(img * 10 + t) * NPIX + (gy << 6) + gx) * FDIM + (fq << 2);
                *(float4*)(outseq + oidx) = hn;
            }
        }
    } else {
        float* ob = out_gates + (size_t)img * NPIX * C4;
#pragma unroll
        for (int i = 0; i < 4; ++i) {
            int pos = pc * 4 + i;
            int gy = by0 + (pos >> 3), gx = bx0 + (pos & 7);
            float4* op = (float4*)(ob + (size_t)((gy << 6) + gx) * C4);
#pragma unroll
            for (int j = 0; j < 4; ++j) op[(cc << 2) + j] = acc[i][j];
        }
    }
}

// ---------------------------------------------------------------------------
// Host: full encoder pipeline on the default stream (graph-capturable).
// ---------------------------------------------------------------------------
extern "C" void kernel_launch(void* const* d_in, const int* in_sizes, int n_in,
                              void* d_out, int out_size) {
    const float* x   = (const float*)d_in[0];
    const float* Wx0 = (const float*)d_in[1];
    const float* Wh0 = (const float*)d_in[2];
    const float* b0  = (const float*)d_in[3];
    const float* Wx1 = (const float*)d_in[4];
    const float* Wh1 = (const float*)d_in[5];
    const float* b1  = (const float*)d_in[6];
    float* out = (float*)d_out;

    float *xg0, *xg1, *out0, *hbase, *cbuf;
    cudaGetSymbolAddress((void**)&xg0,  g_xg0);
    cudaGetSymbolAddress((void**)&xg1,  g_xg1);
    cudaGetSymbolAddress((void**)&out0, g_out0);
    cudaGetSymbolAddress((void**)&hbase, g_h);
    cudaGetSymbolAddress((void**)&cbuf, g_c);
    float* hb[2] = { hbase, hbase + SEG };

    cudaFuncSetAttribute(conv_main<1>, cudaFuncAttributeMaxDynamicSharedMemorySize, 65536);
    cudaFuncSetAttribute(conv_main<0>, cudaFuncAttributeMaxDynamicSharedMemorySize, 65536);

    // Layer 0: batched input conv (Cin=1) for all 80 (b,t) images
    conv_l0<<<dim3(16, 80), 256>>>(x, Wx0, b0, xg0);

    // Layer 0 recurrence
    zero_hc<<<2048, 1024>>>();
    for (int t = 0; t < 10; ++t)
        conv_main<1><<<dim3(64, 8), 256, 65536>>>(
            hb[t & 1], Wh0, xg0, nullptr, cbuf, hb[(t + 1) & 1], out0, t);
    gather_out<<<2048, 1024>>>(out, 0);

    // Layer 1: batched input conv over out0 (80 images, Cin=64)
    conv_main<0><<<dim3(64, 80), 256, 65536>>>(
        out0, Wx1, b1, xg1, nullptr, nullptr, nullptr, 0);

    // Layer 1 recurrence
    zero_hc<<<2048, 1024>>>();
    for (int t = 0; t < 10; ++t)
        conv_main<1><<<dim3(64, 8), 256, 65536>>>(
            hb[t & 1], Wh1, xg1, nullptr, cbuf, hb[(t + 1) & 1], nullptr, t);
    gather_out<<<2048, 1024>>>(out, 1);

    (void)in_sizes; (void)n_in; (void)out_size;
}

// round 7
// speedup vs baseline: 5.2600x; 5.2600x over previous
#include <cuda_runtime.h>
#include <math.h>
#include <stdint.h>

// ---------------------------------------------------------------------------
// B=8, T=10, H=W=64, Cin=1, F=64, 4F=256, k=3x3 SAME.
// Output: [2][2][8][64][64][64] fp32.
// Strategy: legacy mma.sync tf32 (m16n8k8) implicit-GEMM conv.
// Per block: M=64 positions (one image row) x N=256 gates, K=576 consumed as
// 18 stages (9 taps x 2 chunks of 32 input channels). fp32 register accums.
// ---------------------------------------------------------------------------

#define HW    64
#define FDIM  64
#define C4    256
#define NPIX  4096
#define SEG   2097152            // 8*4096*64

__device__ float g_xg0[10 * 8 * NPIX * C4];
__device__ float g_xg1[10 * 8 * NPIX * C4];
__device__ float g_out0[10 * 8 * NPIX * FDIM];
__device__ float g_h[2][SEG];
__device__ float g_c[SEG];
__device__ float g_wt[3 * 576 * 256];   // tf32-rounded Wh0 / Wx1 / Wh1

__device__ __forceinline__ float hsig(float x) {
    return fminf(fmaxf(0.2f * x + 0.5f, 0.0f), 1.0f);
}
__device__ __forceinline__ float tf32r(float v) {
    unsigned u;
    asm("cvt.rna.tf32.f32 %0, %1;" : "=r"(u) : "f"(v));
    return __uint_as_float(u);
}
__device__ __forceinline__ unsigned smem_u32(const void* p) {
    unsigned r;
    asm("{ .reg .u64 t; cvta.to.shared.u64 t, %1; cvt.u32.u64 %0, t; }"
        : "=r"(r) : "l"(p));
    return r;
}

#define MMA_TF32(c, a, b0v, b1v)                                               \
    asm volatile("mma.sync.aligned.m16n8k8.row.col.f32.tf32.tf32.f32 "         \
        "{%0,%1,%2,%3}, {%4,%5,%6,%7}, {%8,%9}, {%0,%1,%2,%3};"                \
        : "+f"(c[0]), "+f"(c[1]), "+f"(c[2]), "+f"(c[3])                       \
        : "r"(a[0]), "r"(a[1]), "r"(a[2]), "r"(a[3]), "r"(b0v), "r"(b1v))

// smem layout (floats): A bufs stride 36/row (64 rows), B bufs stride 264/row
#define AB0   0
#define AB1   2304
#define BB0   4608
#define BB1   13056
#define SMEMF 21504
#define SMEM_BYTES (SMEMF * 4)       // 86016

// ---------------------------------------------------------------------------
__global__ void zero_hc() {
    int i = blockIdx.x * blockDim.x + threadIdx.x;
    if (i < SEG) { g_h[0][i] = 0.0f; g_c[i] = 0.0f; }
}
__global__ void gather_out(float* __restrict__ out, int layer) {
    int i = blockIdx.x * blockDim.x + threadIdx.x;
    if (i < SEG) {
        out[(size_t)layer * 2 * SEG + i]       = g_h[0][i];
        out[(size_t)layer * 2 * SEG + SEG + i] = g_c[i];
    }
}

// Round the three 64->256 weight tensors to tf32 (layout unchanged:
// row r = tap*64 + ic  ->  stage s = r/32 slices are contiguous).
__global__ void prep_w(const float* __restrict__ w0, const float* __restrict__ w1,
                       const float* __restrict__ w2) {
    int idx = blockIdx.x * 256 + threadIdx.x;
    if (idx >= 3 * 576 * 256) return;
    int which = idx / (576 * 256);
    int r     = idx - which * (576 * 256);
    const float* src = (which == 0) ? w0 : (which == 1) ? w1 : w2;
    g_wt[idx] = tf32r(src[r]);
}

// Layer-0 input conv (Cin=1), exact fp32: xg0[img][pix][256] = b0 + conv(x, Wx0)
__global__ void conv_l0(const float* __restrict__ x, const float* __restrict__ w,
                        const float* __restrict__ b, float* __restrict__ xg) {
    __shared__ float ps[18 * 18];
    __shared__ float ws[9 * C4];
    int img = blockIdx.y;
    int by0 = (blockIdx.x >> 2) * 16, bx0 = (blockIdx.x & 3) * 16;
    int tid = threadIdx.x;
    for (int i = tid; i < 324; i += 256) {
        int ly = i / 18, lx = i - ly * 18;
        int gy = by0 + ly - 1, gx = bx0 + lx - 1;
        float v = 0.0f;
        if (gy >= 0 && gy < HW && gx >= 0 && gx < HW)
            v = x[(size_t)img * NPIX + gy * HW + gx];
        ps[i] = v;
    }
    for (int i = tid; i < 9 * C4; i += 256) ws[i] = w[i];
    __syncthreads();
    float wr[9];
#pragma unroll
    for (int tp = 0; tp < 9; ++tp) wr[tp] = ws[tp * C4 + tid];
    float bv = b[tid];
    for (int p = 0; p < 256; ++p) {
        int py = p >> 4, px = p & 15;
        float a = bv;
#pragma unroll
        for (int tp = 0; tp < 9; ++tp) {
            int dy = tp / 3, dx = tp - 3 * dy;
            a += ps[(py + dy) * 18 + (px + dx)] * wr[tp];
        }
        xg[((size_t)img * NPIX + (by0 + py) * HW + (bx0 + px)) * C4 + tid] = a;
    }
}

// ---------------------------------------------------------------------------
// tf32 mma.sync conv block. MODE 1: LSTM step; MODE 0: gates = conv + bias.
// 8 warps as 2(M) x 4(N); warp tile 32x64; 64 fp32 accumulators per thread.
// A smem stride 36 -> bank (4p+k)&31 conflict-free; B stride 264 -> bank
// (8k+n)&31 conflict-free for the fragment access patterns.
// ---------------------------------------------------------------------------
template <int MODE>
__global__ void __launch_bounds__(256, 2)
mm_conv(const float* __restrict__ in, const float* __restrict__ wt,
        const float* __restrict__ xg_or_bias, float* __restrict__ gout,
        float* __restrict__ cbuf, float* __restrict__ hout,
        float* __restrict__ outseq, int tstep) {
    extern __shared__ float smf[];
    unsigned sbase = smem_u32(smf);
    int tid = threadIdx.x;
    int wid = tid >> 5, lane = tid & 31;
    int g = lane >> 2, tg = lane & 3;
    int mw = wid >> 2, nw = wid & 3;
    int m_base = mw * 32, n_base = nw * 64;
    int img = blockIdx.y;
    int y0 = blockIdx.x;                       // image row handled by block
    const float* inb = in + (size_t)img * (NPIX * FDIM);

    float acc[2][8][4];
#pragma unroll
    for (int mi = 0; mi < 2; ++mi)
#pragma unroll
        for (int ni = 0; ni < 8; ++ni)
#pragma unroll
            for (int r = 0; r < 4; ++r) acc[mi][ni][r] = 0.0f;

    // ---- staging lambdas -------------------------------------------------
    auto issueB = [&](int s, int buf) {
        const float* wp = wt + (size_t)s * 8192;
        unsigned dbase = sbase + (buf ? BB1 : BB0) * 4;
#pragma unroll
        for (int i = 0; i < 8; ++i) {
            int idx = tid + i * 256;              // float4 index 0..2047
            int row = idx >> 6, c4 = idx & 63;
            unsigned daddr = dbase + (unsigned)(row * 264 + c4 * 4) * 4;
            const float4* src = (const float4*)wp + idx;
            asm volatile("cp.async.ca.shared.global [%0], [%1], 16;"
                         :: "r"(daddr), "l"(src));
        }
    };
    float4 va[2];
    auto ldA = [&](int s) {
        int tap = s >> 1, ch0 = (s & 1) * 32;
        int dy = tap / 3 - 1, dx = tap % 3 - 1;
        int y = y0 + dy;
#pragma unroll
        for (int i = 0; i < 2; ++i) {
            int q = tid + i * 256;                // 0..511
            int p = q >> 3, f = q & 7;
            int xx = p + dx;
            float4 v = make_float4(0.f, 0.f, 0.f, 0.f);
            if ((unsigned)y < 64u && (unsigned)xx < 64u)
                v = *(const float4*)(inb + (size_t)(((y << 6) + xx) * 64 + ch0 + f * 4));
            v.x = tf32r(v.x); v.y = tf32r(v.y); v.z = tf32r(v.z); v.w = tf32r(v.w);
            va[i] = v;
        }
    };
    auto stsA = [&](int buf) {
        float* ab = smf + (buf ? AB1 : AB0);
#pragma unroll
        for (int i = 0; i < 2; ++i) {
            int q = tid + i * 256;
            int p = q >> 3, f = q & 7;
            *(float4*)(ab + p * 36 + f * 4) = va[i];
        }
    };

    // ---- pipeline --------------------------------------------------------
    ldA(0);
    issueB(0, 0);
    asm volatile("cp.async.commit_group;");

    for (int s = 0; s < 18; ++s) {
        int cur = s & 1;
        __syncthreads();                       // prev compute done with nxt buf
        if (s + 1 < 18) {
            issueB(s + 1, 1 - cur);
            asm volatile("cp.async.commit_group;");
        }
        stsA(cur);
        if (s + 1 < 18) ldA(s + 1);
        asm volatile("cp.async.wait_group 1;"); // B(s) resident
        __syncthreads();                        // A(s)/B(s) visible to all

        const float* Ab = smf + (cur ? AB1 : AB0);
        const float* Bb = smf + (cur ? BB1 : BB0);
#pragma unroll
        for (int kf = 0; kf < 4; ++kf) {
            int k0 = kf * 8;
            unsigned a[2][4];
#pragma unroll
            for (int mi = 0; mi < 2; ++mi) {
                const float* ap = Ab + (m_base + mi * 16 + g) * 36 + k0 + tg;
                a[mi][0] = __float_as_uint(ap[0]);
                a[mi][1] = __float_as_uint(ap[8 * 36]);
                a[mi][2] = __float_as_uint(ap[4]);
                a[mi][3] = __float_as_uint(ap[8 * 36 + 4]);
            }
#pragma unroll
            for (int ni = 0; ni < 8; ++ni) {
                const float* bp = Bb + (k0 + tg) * 264 + n_base + ni * 8 + g;
                unsigned b0 = __float_as_uint(bp[0]);
                unsigned b1 = __float_as_uint(bp[4 * 264]);
                MMA_TF32(acc[0][ni], a[0], b0, b1);
                MMA_TF32(acc[1][ni], a[1], b0, b1);
            }
        }
    }

    // ---- epilogue --------------------------------------------------------
    if (MODE == 0) {
        const float* bias = xg_or_bias;
        float* ob = gout + ((size_t)img * NPIX + y0 * 64) * 256;
#pragma unroll
        for (int mi = 0; mi < 2; ++mi) {
#pragma unroll
            for (int ni = 0; ni < 8; ++ni) {
                int r0 = m_base + mi * 16 + g;
                int cl = n_base + ni * 8 + 2 * tg;
                float2 bb = *(const float2*)(bias + cl);
                float2 v0 = make_float2(acc[mi][ni][0] + bb.x, acc[mi][ni][1] + bb.y);
                float2 v1 = make_float2(acc[mi][ni][2] + bb.x, acc[mi][ni][3] + bb.y);
                *(float2*)(ob + (size_t)r0 * 256 + cl)       = v0;
                *(float2*)(ob + (size_t)(r0 + 8) * 256 + cl) = v1;
            }
        }
    } else {
        // exchange gates through smem (stride 264), then combine
        __syncthreads();                       // last compute done reading bufs
#pragma unroll
        for (int mi = 0; mi < 2; ++mi) {
#pragma unroll
            for (int ni = 0; ni < 8; ++ni) {
                int r0 = m_base + mi * 16 + g;
                int cl = n_base + ni * 8 + 2 * tg;
                *(float2*)(smf + r0 * 264 + cl) =
                    make_float2(acc[mi][ni][0], acc[mi][ni][1]);
                *(float2*)(smf + (r0 + 8) * 264 + cl) =
                    make_float2(acc[mi][ni][2], acc[mi][ni][3]);
            }
        }
        __syncthreads();
        int p = tid >> 2, f0 = (tid & 3) * 16;
        int pix = y0 * 64 + p;
        const float* xgp = xg_or_bias + ((size_t)(img * 10 + tstep) * NPIX + pix) * 256;
        float* cp = cbuf + ((size_t)img * NPIX + pix) * 64;
        float* hp = hout + ((size_t)img * NPIX + pix) * 64;
        float* op = outseq ? outseq + ((size_t)(img * 10 + tstep) * NPIX + pix) * 64
                           : (float*)0;
        const float* gm = smf + p * 264;
#pragma unroll
        for (int j = 0; j < 4; ++j) {
            int f = f0 + j * 4;
            float4 vi = *(const float4*)(gm + f);
            float4 vf = *(const float4*)(gm + 64 + f);
            float4 vg = *(const float4*)(gm + 128 + f);
            float4 vo = *(const float4*)(gm + 192 + f);
            float4 xi = *(const float4*)(xgp + f);
            float4 xf = *(const float4*)(xgp + 64 + f);
            float4 xgv = *(const float4*)(xgp + 128 + f);
            float4 xo = *(const float4*)(xgp + 192 + f);
            float4 co = *(const float4*)(cp + f);
            float4 cn, hn;
            cn.x = hsig(vf.x + xf.x) * co.x + hsig(vi.x + xi.x) * tanhf(vg.x + xgv.x);
            cn.y = hsig(vf.y + xf.y) * co.y + hsig(vi.y + xi.y) * tanhf(vg.y + xgv.y);
            cn.z = hsig(vf.z + xf.z) * co.z + hsig(vi.z + xi.z) * tanhf(vg.z + xgv.z);
            cn.w = hsig(vf.w + xf.w) * co.w + hsig(vi.w + xi.w) * tanhf(vg.w + xgv.w);
            hn.x = hsig(vo.x + xo.x) * tanhf(cn.x);
            hn.y = hsig(vo.y + xo.y) * tanhf(cn.y);
            hn.z = hsig(vo.z + xo.z) * tanhf(cn.z);
            hn.w = hsig(vo.w + xo.w) * tanhf(cn.w);
            *(float4*)(cp + f) = cn;
            *(float4*)(hp + f) = hn;
            if (op) *(float4*)(op + f) = hn;
        }
    }
}

// ---------------------------------------------------------------------------
extern "C" void kernel_launch(void* const* d_in, const int* in_sizes, int n_in,
                              void* d_out, int out_size) {
    const float* x   = (const float*)d_in[0];
    const float* Wx0 = (const float*)d_in[1];
    const float* Wh0 = (const float*)d_in[2];
    const float* b0  = (const float*)d_in[3];
    const float* Wx1 = (const float*)d_in[4];
    const float* Wh1 = (const float*)d_in[5];
    const float* b1  = (const float*)d_in[6];
    float* out = (float*)d_out;

    float *xg0, *xg1, *out0, *hbase, *cb, *wt;
    cudaGetSymbolAddress((void**)&xg0,   g_xg0);
    cudaGetSymbolAddress((void**)&xg1,   g_xg1);
    cudaGetSymbolAddress((void**)&out0,  g_out0);
    cudaGetSymbolAddress((void**)&hbase, g_h);
    cudaGetSymbolAddress((void**)&cb,    g_c);
    cudaGetSymbolAddress((void**)&wt,    g_wt);
    float* hb[2] = { hbase, hbase + SEG };

    cudaFuncSetAttribute(mm_conv<1>, cudaFuncAttributeMaxDynamicSharedMemorySize, SMEM_BYTES);
    cudaFuncSetAttribute(mm_conv<0>, cudaFuncAttributeMaxDynamicSharedMemorySize, SMEM_BYTES);

    // tf32-round weights: g_wt[0]=Wh0, [1]=Wx1, [2]=Wh1
    prep_w<<<1728, 256>>>(Wh0, Wx1, Wh1);

    // Layer-0 input conv (exact fp32)
    conv_l0<<<dim3(16, 80), 256>>>(x, Wx0, b0, xg0);

    // Layer 0 recurrence
    zero_hc<<<2048, 1024>>>();
    for (int t = 0; t < 10; ++t)
        mm_conv<1><<<dim3(64, 8), 256, SMEM_BYTES>>>(
            hb[t & 1], wt, xg0, nullptr, cb, hb[(t + 1) & 1], out0, t);
    gather_out<<<2048, 1024>>>(out, 0);

    // Layer-1 batched input conv over 80 images
    mm_conv<0><<<dim3(64, 80), 256, SMEM_BYTES>>>(
        out0, wt + 576 * 256, b1, xg1, nullptr, nullptr, nullptr, 0);

    // Layer 1 recurrence
    zero_hc<<<2048, 1024>>>();
    for (int t = 0; t < 10; ++t)
        mm_conv<1><<<dim3(64, 8), 256, SMEM_BYTES>>>(
            hb[t & 1], wt + 2 * 576 * 256, xg1, nullptr, cb, hb[(t + 1) & 1], nullptr, t);
    gather_out<<<2048, 1024>>>(out, 1);

    (void)in_sizes; (void)n_in; (void)out_size;
}